// round 1
// baseline (speedup 1.0000x reference)
#include <cuda_runtime.h>
#include <math_constants.h>

// KNNRegressor: out[q] = mean of y_train over the k=32 nearest train points.
// Score surrogate: s(q,c) = |t_c|^2 - 2 q·t_c   (|q|^2 dropped: per-query
// constant, cannot change ordering). fp32 exact-ish to match reference top-k.
//
// Kernel 1: t_sq[c] = |X_train[c]|^2
// Kernel 2: fused SGEMM (64q x 128c tiles, D=128) + streaming warp-register
//           top-32 per query, candidate dim split across SPLITS CTAs.
// Kernel 3: merge SPLITS*32 candidates per query -> top-32 -> mean(y).

#define DDIM   128
#define QTILE  64
#define CTILE  128
#define SPLITS 8
#define NTHR   256
#define XS     130          // smem row stride in floats (bank-conflict-free)
#define KSEL   32
#define NMAX   100000
#define QMAX   4096

__device__ float g_tsq [NMAX];
__device__ float g_dist[QMAX * SPLITS * KSEL];
__device__ int   g_idx [QMAX * SPLITS * KSEL];

// ---------------------------------------------------------------- kernel 1
__global__ void tsq_kernel(const float* __restrict__ X, int n) {
    int row  = blockIdx.x * 8 + (threadIdx.x >> 5);
    int lane = threadIdx.x & 31;
    if (row >= n) return;
    float4 v = reinterpret_cast<const float4*>(X + (size_t)row * DDIM)[lane];
    float s = v.x * v.x + v.y * v.y + v.z * v.z + v.w * v.w;
    #pragma unroll
    for (int o = 16; o; o >>= 1) s += __shfl_xor_sync(0xffffffffu, s, o);
    if (lane == 0) g_tsq[row] = s;
}

// ---------------------------------------------------------------- kernel 2
__global__ void __launch_bounds__(NTHR, 2)
knn_main(const float* __restrict__ Qm, const float* __restrict__ X,
         int n, int q_total) {
    extern __shared__ float smem[];
    float* q_s = smem;                 // [QTILE][XS]
    float* x_s = smem + QTILE * XS;    // [CTILE][XS], reused as score buffer

    const int tid  = threadIdx.x;
    const int lane = tid & 31;
    const int warp = tid >> 5;
    const int TX   = tid & 15;         // candidate group (8 cands, stride 16)
    const int TY   = tid >> 4;         // query group (4 queries)

    const int qbase = blockIdx.x * QTILE;
    const int per   = n / SPLITS;                 // 12500 (exact for N=100000)
    const int sbase = blockIdx.y * per;
    const int send  = (blockIdx.y == SPLITS - 1) ? n : sbase + per;

    // Load query tile once (transposition-free: [q][k], row stride XS).
    for (int i = tid; i < QTILE * (DDIM / 2); i += NTHR) {
        int q  = i >> 6;               // DDIM/2 = 64 float2 per row
        int kg = i & 63;
        int qq = qbase + q; if (qq >= q_total) qq = q_total - 1;
        float2 v = *reinterpret_cast<const float2*>(Qm + (size_t)qq * DDIM + kg * 2);
        *reinterpret_cast<float2*>(q_s + q * XS + kg * 2) = v;
    }

    // Warp-held sorted top-32 list per query (8 queries per warp).
    float ld[8];
    int   li[8];
    #pragma unroll
    for (int j = 0; j < 8; j++) { ld[j] = CUDART_INF_F; li[j] = 0; }

    for (int cb = sbase; cb < send; cb += CTILE) {
        __syncthreads();               // selection of previous chunk done
        // Load X chunk [CTILE][DDIM] (zero-fill OOB rows).
        for (int i = tid; i < CTILE * (DDIM / 2); i += NTHR) {
            int c  = i >> 6;
            int kg = i & 63;
            float2 v = make_float2(0.f, 0.f);
            if (cb + c < send)
                v = *reinterpret_cast<const float2*>(X + (size_t)(cb + c) * DDIM + kg * 2);
            *reinterpret_cast<float2*>(x_s + c * XS + kg * 2) = v;
        }
        __syncthreads();

        // 64x128 fp32 GEMM tile; thread micro-tile 4q x 8c.
        float acc[4][8];
        #pragma unroll
        for (int j = 0; j < 4; j++)
            #pragma unroll
            for (int i2 = 0; i2 < 8; i2++) acc[j][i2] = 0.f;

        #pragma unroll 4
        for (int k = 0; k < DDIM; k += 2) {
            float2 a[4], b[8];
            #pragma unroll
            for (int j = 0; j < 4; j++)
                a[j] = *reinterpret_cast<const float2*>(q_s + (TY * 4 + j) * XS + k);
            #pragma unroll
            for (int i2 = 0; i2 < 8; i2++)
                b[i2] = *reinterpret_cast<const float2*>(x_s + (TX + 16 * i2) * XS + k);
            #pragma unroll
            for (int j = 0; j < 4; j++)
                #pragma unroll
                for (int i2 = 0; i2 < 8; i2++) {
                    acc[j][i2] = fmaf(a[j].x, b[i2].x, acc[j][i2]);
                    acc[j][i2] = fmaf(a[j].y, b[i2].y, acc[j][i2]);
                }
        }
        __syncthreads();

        // Scores into x_s (reuse): s = tsq[c] - 2*dot.  OOB -> +inf.
        #pragma unroll
        for (int j = 0; j < 4; j++) {
            int q = TY * 4 + j;
            #pragma unroll
            for (int i2 = 0; i2 < 8; i2++) {
                int c = TX + 16 * i2;
                float sc = (cb + c < send) ? (g_tsq[cb + c] - 2.f * acc[j][i2])
                                           : CUDART_INF_F;
                x_s[q * CTILE + c] = sc;
            }
        }
        __syncthreads();

        // Streaming top-32 update: warp w owns queries 8w..8w+7.
        #pragma unroll
        for (int j = 0; j < 8; j++) {
            int q = warp * 8 + j;
            float thr = __shfl_sync(0xffffffffu, ld[j], 31);
            #pragma unroll
            for (int r = 0; r < 4; r++) {
                float val = x_s[q * CTILE + r * 32 + lane];
                unsigned pass = __ballot_sync(0xffffffffu, val < thr);
                while (pass) {
                    int src = __ffs(pass) - 1;
                    pass &= pass - 1;
                    float v  = __shfl_sync(0xffffffffu, val, src);
                    int   gi = cb + r * 32 + src;
                    unsigned m = __ballot_sync(0xffffffffu, v < ld[j]);
                    if (m) {
                        int p = __ffs(m) - 1;
                        float dn = __shfl_up_sync(0xffffffffu, ld[j], 1);
                        int   in = __shfl_up_sync(0xffffffffu, li[j], 1);
                        if (lane > p)       { ld[j] = dn; li[j] = in; }
                        else if (lane == p) { ld[j] = v;  li[j] = gi; }
                    }
                    thr = __shfl_sync(0xffffffffu, ld[j], 31);
                }
            }
        }
    }

    // Emit per-(query, split) sorted top-32.
    #pragma unroll
    for (int j = 0; j < 8; j++) {
        int q = qbase + warp * 8 + j;
        if (q < q_total) {
            int off = (q * SPLITS + blockIdx.y) * KSEL + lane;
            g_dist[off] = ld[j];
            g_idx[off]  = li[j];
        }
    }
}

// ---------------------------------------------------------------- kernel 3
__global__ void knn_merge(const float* __restrict__ y, float* __restrict__ out,
                          int q_total) {
    int q    = blockIdx.x * (blockDim.x >> 5) + (threadIdx.x >> 5);
    int lane = threadIdx.x & 31;
    if (q >= q_total) return;

    float ld = CUDART_INF_F;
    int   li = 0;
    const float* dp = g_dist + (size_t)q * SPLITS * KSEL;
    const int*   ip = g_idx  + (size_t)q * SPLITS * KSEL;

    for (int s = 0; s < SPLITS; s++) {
        float val = dp[s * KSEL + lane];
        int   vi  = ip[s * KSEL + lane];
        float thr = __shfl_sync(0xffffffffu, ld, 31);
        unsigned pass = __ballot_sync(0xffffffffu, val < thr);
        while (pass) {
            int src = __ffs(pass) - 1;
            pass &= pass - 1;
            float v  = __shfl_sync(0xffffffffu, val, src);
            int   gi = __shfl_sync(0xffffffffu, vi,  src);
            unsigned m = __ballot_sync(0xffffffffu, v < ld);
            if (m) {
                int p = __ffs(m) - 1;
                float dn = __shfl_up_sync(0xffffffffu, ld, 1);
                int   in = __shfl_up_sync(0xffffffffu, li, 1);
                if (lane > p)       { ld = dn; li = in; }
                else if (lane == p) { ld = v;  li = gi; }
            }
            thr = __shfl_sync(0xffffffffu, ld, 31);
        }
    }

    float yv = y[li];
    #pragma unroll
    for (int o = 16; o; o >>= 1) yv += __shfl_xor_sync(0xffffffffu, yv, o);
    if (lane == 0) out[q] = yv * (1.0f / (float)KSEL);
}

// ---------------------------------------------------------------- launcher
extern "C" void kernel_launch(void* const* d_in, const int* in_sizes, int n_in,
                              void* d_out, int out_size) {
    const float* Qm = (const float*)d_in[0];
    const float* X  = (const float*)d_in[1];
    const float* y  = (const float*)d_in[2];
    const int q_total = in_sizes[0] / DDIM;   // 4096
    const int n       = in_sizes[2];          // 100000
    float* out = (float*)d_out;

    // t_sq
    tsq_kernel<<<(n + 7) / 8, 256>>>(X, n);

    // fused GEMM + streaming top-k
    const int smem_bytes = (QTILE + CTILE) * XS * (int)sizeof(float); // 99840
    static int smem_set = 0;
    if (!smem_set) {
        cudaFuncSetAttribute(knn_main, cudaFuncAttributeMaxDynamicSharedMemorySize,
                             smem_bytes);
        smem_set = 1;
    }
    dim3 grid((q_total + QTILE - 1) / QTILE, SPLITS);
    knn_main<<<grid, NTHR, smem_bytes>>>(Qm, X, n, q_total);

    // merge + mean(y)
    knn_merge<<<(q_total + 7) / 8, 256>>>(y, out, q_total);
}